// round 5
// baseline (speedup 1.0000x reference)
#include <cuda_runtime.h>
#include <cuda_bf16.h>
#include <stdint.h>

#define NTOK 4096
#define NEDGE 131072
#define TNUM 8
#define RNUM 16
#define HNUM 8
#define BNUM 21
#define SEEDS 128
#define CAP 96            // per-row edge-list capacity (avg degree = 32, max ~66)

// ---------------------------------------------------------------------------
// Device scratch (.bss => zero at module load). INVARIANT: every launch both
// finds and leaves g_cursor / g_done / g_rows_done / g_overcnt all zero.
// ---------------------------------------------------------------------------
__device__ int g_cursor[NTOK];         // per-row raw edge count
__device__ int g_done[NTOK];           // per-row fill-block arrival count
__device__ int g_rows_done;            // completed-row count
__device__ int g_elist[NTOK * CAP];    // packed (dst << 4) | rel, per row
__device__ int g_overcnt;              // overflow edge count
__device__ int g_over[NEDGE];          // packed (src << 16) | (dst << 4) | rel

// ---------------------------------------------------------------------------
__device__ __forceinline__ int bucketize(float dt) {
    float s  = (dt > 0.0f) ? 1.0f : ((dt < 0.0f) ? -1.0f : 0.0f);
    float sl = s * log1pf(fabsf(dt) + 1e-6f);
    float c  = fminf(fmaxf(sl, -5.0f), 5.0f);
    float norm = (c + 5.0f) / (10.0f + 1e-9f);
    int idx = (int)floorf(norm * (float)(BNUM - 1));
    idx = idx < 0 ? 0 : idx;
    idx = idx > (BNUM - 1) ? (BNUM - 1) : idx;
    return idx;
}

// ---------------------------------------------------------------------------
// One-pass per-row edge-list build (cursors are zero on entry by invariant)
// ---------------------------------------------------------------------------
__global__ __launch_bounds__(256) void build_kernel(
    const int* __restrict__ edge_src,
    const int* __restrict__ edge_dst,
    const int* __restrict__ edge_rel)
{
    int e = blockIdx.x * blockDim.x + threadIdx.x;
    if (e >= NEDGE) return;
    int s = edge_src[e];
    int d = edge_dst[e];
    int r = edge_rel[e];
    int pos = atomicAdd(&g_cursor[s], 1);
    if (pos < CAP) {
        g_elist[s * CAP + pos] = (d << 4) | r;
    } else {
        int o = atomicAdd(&g_overcnt, 1);
        g_over[o] = (s << 16) | (d << 4) | r;
    }
}

// ---------------------------------------------------------------------------
// Fill kernel: one block per (i, h) row.
//   Phase 1: direct coalesced float4 stores (the proven 81us loop).
//   Phase 2: this row's edges via L2-hit atomicAdd into the fresh row,
//            plus any overflow entries for this row (normally none).
//   Phase 3: counter restoration — last of the row's 8 blocks zeroes the
//            row cursor; globally-last row zeroes g_overcnt.
// ---------------------------------------------------------------------------
__global__ __launch_bounds__(256) void fill_kernel(
    const int*   __restrict__ token_type,
    const float* __restrict__ time_vec,
    const float* __restrict__ typepair_bias,  // (T, T, H)
    const float* __restrict__ temp_bias,      // (B, H)
    const float* __restrict__ adj_rel_bias,   // (R, H)
    float*       __restrict__ out)            // (H, N, N)
{
    const int i = blockIdx.x;
    const int h = blockIdx.y;
    const int tid = threadIdx.x;

    __shared__ float val8[TNUM];
    __shared__ float tb[BNUM];
    __shared__ float relb[RNUM];

    if (tid < TNUM) {
        const int tt_i = token_type[i];
        val8[tid] = typepair_bias[(tt_i * TNUM + tid) * HNUM + h];
    }
    if (tid < BNUM) tb[tid]   = temp_bias[tid * HNUM + h];
    if (tid < RNUM) relb[tid] = adj_rel_bias[tid * HNUM + h];
    __syncthreads();

    const bool  is_seed = (i < SEEDS);
    const float ti      = time_vec[i];

    float* __restrict__ orow =
        out + ((size_t)h * NTOK + (size_t)i) * (size_t)NTOK;

    // Phase 1: 4096 elements / (256 thr * 4) = 4 float4 stores per thread
    #pragma unroll
    for (int j0 = tid * 4; j0 < NTOK; j0 += 256 * 4) {
        const int4 t4 = *reinterpret_cast<const int4*>(token_type + j0);
        float4 v;
        v.x = val8[t4.x];
        v.y = val8[t4.y];
        v.z = val8[t4.z];
        v.w = val8[t4.w];
        if (is_seed) {
            const float4 tv = *reinterpret_cast<const float4*>(time_vec + j0);
            v.x += tb[bucketize(tv.x - ti)];
            v.y += tb[bucketize(tv.y - ti)];
            v.z += tb[bucketize(tv.z - ti)];
            v.w += tb[bucketize(tv.w - ti)];
        }
        *reinterpret_cast<float4*>(orow + j0) = v;
    }
    __syncthreads();   // row fully stored before RMW

    // Phase 2a: this row's edges — L2-hit atomics into the fresh row
    const int count = min(g_cursor[i], CAP);
    for (int e = tid; e < count; e += 256) {
        const int p = g_elist[i * CAP + e];
        atomicAdd(orow + (p >> 4), relb[p & 15]);
    }

    // Phase 2b: overflow entries for this row (normally g_overcnt == 0)
    const int on = g_overcnt;
    for (int e = tid; e < on; e += 256) {
        const int p = g_over[e];
        if ((p >> 16) == i)
            atomicAdd(orow + ((p >> 4) & 0xFFF), relb[p & 15]);
    }

    // Phase 3: restore the zero-invariant for the next launch
    __syncthreads();
    if (tid == 0) {
        __threadfence();   // order this block's reads/adds before arrivals
        int prev = atomicAdd(&g_done[i], 1);
        if (prev == HNUM - 1) {          // last of the 8 blocks for row i
            g_cursor[i] = 0;
            g_done[i]   = 0;
            __threadfence();
            int pr = atomicAdd(&g_rows_done, 1);
            if (pr == NTOK - 1) {        // globally last row
                g_overcnt   = 0;
                g_rows_done = 0;
            }
        }
    }
}

// ---------------------------------------------------------------------------
extern "C" void kernel_launch(void* const* d_in, const int* in_sizes, int n_in,
                              void* d_out, int out_size)
{
    const int*   token_type    = (const int*)  d_in[0];
    const int*   edge_src      = (const int*)  d_in[1];
    const int*   edge_dst      = (const int*)  d_in[2];
    const int*   edge_rel      = (const int*)  d_in[3];
    const float* time_vec      = (const float*)d_in[4];
    const float* adj_rel_bias  = (const float*)d_in[n_in - 3];
    const float* typepair_bias = (const float*)d_in[n_in - 2];
    const float* temp_bias     = (const float*)d_in[n_in - 1];
    float* out = (float*)d_out;

    build_kernel<<<(NEDGE + 255) / 256, 256>>>(edge_src, edge_dst, edge_rel);

    dim3 grid_fill(NTOK, HNUM);
    fill_kernel<<<grid_fill, 256>>>(token_type, time_vec, typepair_bias,
                                    temp_bias, adj_rel_bias, out);
}

// round 7
// speedup vs baseline: 1.4919x; 1.4919x over previous
#include <cuda_runtime.h>
#include <cuda_bf16.h>
#include <stdint.h>

#define NTOK 4096
#define NEDGE 131072
#define TNUM 8
#define RNUM 16
#define HNUM 8
#define BNUM 21
#define SEEDS 128
#define CAP 96            // per-row edge-list capacity (avg degree = 32, max ~66)

// ---------------------------------------------------------------------------
// Device scratch (no allocation allowed). Zeroed by zero_kernel each launch.
// ---------------------------------------------------------------------------
__device__ int g_cursor[NTOK];         // per-row raw edge count
__device__ int g_elist[NTOK * CAP];    // packed (dst << 4) | rel, per row
__device__ int g_overcnt;              // overflow edge count
__device__ int g_over[NEDGE];          // packed (src << 16) | (dst << 4) | rel

// ---------------------------------------------------------------------------
__device__ __forceinline__ int bucketize(float dt) {
    float s  = (dt > 0.0f) ? 1.0f : ((dt < 0.0f) ? -1.0f : 0.0f);
    float sl = s * log1pf(fabsf(dt) + 1e-6f);
    float c  = fminf(fmaxf(sl, -5.0f), 5.0f);
    float norm = (c + 5.0f) / (10.0f + 1e-9f);
    int idx = (int)floorf(norm * (float)(BNUM - 1));
    idx = idx < 0 ? 0 : idx;
    idx = idx > (BNUM - 1) ? (BNUM - 1) : idx;
    return idx;
}

// ---------------------------------------------------------------------------
// Zero cursors + overflow counter (16 KB, trivial)
// ---------------------------------------------------------------------------
__global__ __launch_bounds__(256) void zero_kernel() {
    int i = blockIdx.x * blockDim.x + threadIdx.x;
    if (i < NTOK) g_cursor[i] = 0;
    if (i == 0)   g_overcnt = 0;
}

// ---------------------------------------------------------------------------
// One-pass per-row edge-list build
// ---------------------------------------------------------------------------
__global__ __launch_bounds__(256) void build_kernel(
    const int* __restrict__ edge_src,
    const int* __restrict__ edge_dst,
    const int* __restrict__ edge_rel)
{
    int e = blockIdx.x * blockDim.x + threadIdx.x;
    if (e >= NEDGE) return;
    int s = edge_src[e];
    int d = edge_dst[e];
    int r = edge_rel[e];
    int pos = atomicAdd(&g_cursor[s], 1);
    if (pos < CAP) {
        g_elist[s * CAP + pos] = (d << 4) | r;
    } else {
        int o = atomicAdd(&g_overcnt, 1);
        g_over[o] = (s << 16) | (d << 4) | r;
    }
}

// ---------------------------------------------------------------------------
// Fill kernel: one block per (i, h) row. NO fences, NO end-of-kernel
// counter restoration (the R5 gpu-scope __threadfence caused per-block L1D
// flushes via CCTL.IVALL and throttled the store stream — never again).
//   Phase 1: direct coalesced float4 stores (the proven 81us loop).
//   Phase 2a: this row's edges via L2-hit atomicAdd into the fresh row.
//   Phase 2b: overflow entries for this row (normally zero; visibility via
//             stream ordering of build -> fill).
// ---------------------------------------------------------------------------
__global__ __launch_bounds__(256) void fill_kernel(
    const int*   __restrict__ token_type,
    const float* __restrict__ time_vec,
    const float* __restrict__ typepair_bias,  // (T, T, H)
    const float* __restrict__ temp_bias,      // (B, H)
    const float* __restrict__ adj_rel_bias,   // (R, H)
    float*       __restrict__ out)            // (H, N, N)
{
    const int i = blockIdx.x;
    const int h = blockIdx.y;
    const int tid = threadIdx.x;

    __shared__ float val8[TNUM];
    __shared__ float tb[BNUM];
    __shared__ float relb[RNUM];

    if (tid < TNUM) {
        const int tt_i = token_type[i];
        val8[tid] = typepair_bias[(tt_i * TNUM + tid) * HNUM + h];
    }
    if (tid < BNUM) tb[tid]   = temp_bias[tid * HNUM + h];
    if (tid < RNUM) relb[tid] = adj_rel_bias[tid * HNUM + h];
    __syncthreads();

    const bool  is_seed = (i < SEEDS);
    const float ti      = time_vec[i];

    float* __restrict__ orow =
        out + ((size_t)h * NTOK + (size_t)i) * (size_t)NTOK;

    // Phase 1: 4096 elements / (256 thr * 4) = 4 float4 stores per thread
    #pragma unroll
    for (int j0 = tid * 4; j0 < NTOK; j0 += 256 * 4) {
        const int4 t4 = *reinterpret_cast<const int4*>(token_type + j0);
        float4 v;
        v.x = val8[t4.x];
        v.y = val8[t4.y];
        v.z = val8[t4.z];
        v.w = val8[t4.w];
        if (is_seed) {
            const float4 tv = *reinterpret_cast<const float4*>(time_vec + j0);
            v.x += tb[bucketize(tv.x - ti)];
            v.y += tb[bucketize(tv.y - ti)];
            v.z += tb[bucketize(tv.z - ti)];
            v.w += tb[bucketize(tv.w - ti)];
        }
        *reinterpret_cast<float4*>(orow + j0) = v;
    }
    __syncthreads();   // row fully stored (visible in L2) before RMW

    // Phase 2a: this row's edges — L2-hit atomics into the fresh row
    const int count = min(g_cursor[i], CAP);
    for (int e = tid; e < count; e += 256) {
        const int p = g_elist[i * CAP + e];
        atomicAdd(orow + (p >> 4), relb[p & 15]);
    }

    // Phase 2b: overflow entries for this row (normally g_overcnt == 0)
    const int on = g_overcnt;
    for (int e = tid; e < on; e += 256) {
        const int p = g_over[e];
        if ((p >> 16) == i)
            atomicAdd(orow + ((p >> 4) & 0xFFF), relb[p & 15]);
    }
}

// ---------------------------------------------------------------------------
extern "C" void kernel_launch(void* const* d_in, const int* in_sizes, int n_in,
                              void* d_out, int out_size)
{
    const int*   token_type    = (const int*)  d_in[0];
    const int*   edge_src      = (const int*)  d_in[1];
    const int*   edge_dst      = (const int*)  d_in[2];
    const int*   edge_rel      = (const int*)  d_in[3];
    const float* time_vec      = (const float*)d_in[4];
    const float* adj_rel_bias  = (const float*)d_in[n_in - 3];
    const float* typepair_bias = (const float*)d_in[n_in - 2];
    const float* temp_bias     = (const float*)d_in[n_in - 1];
    float* out = (float*)d_out;

    zero_kernel<<<(NTOK + 255) / 256, 256>>>();
    build_kernel<<<(NEDGE + 255) / 256, 256>>>(edge_src, edge_dst, edge_rel);

    dim3 grid_fill(NTOK, HNUM);
    fill_kernel<<<grid_fill, 256>>>(token_type, time_vec, typepair_bias,
                                    temp_bias, adj_rel_bias, out);
}